// round 5
// baseline (speedup 1.0000x reference)
#include <cuda_runtime.h>

// TripletLoss2: B=4096 rows, D=4096 fp32 features.
// loss_i = hinge( s_near - s_far + 0.5*((l_i-l_far)^2 - (l_i-l_near)^2) )
// out = sum_i loss_i
//
// R5: wave-balance + tail trim.
//  - 2048 CTAs x 128 threads; each CTA = 2 rows, each row split across 2 warps.
//    13.84 CTAs/SM -> last-wave imbalance 3.7% (was 14% at 1024 CTAs).
//  - Per-CTA sum (fixed order) -> g_cta[2048]; last CTA scans 2048 (was 4096).

#define NROWS 4096
#define NDIM  4096
#define MARGIN 0.5f
#define ROWS_PER_CTA 2
#define NCTAS (NROWS / ROWS_PER_CTA)   // 2048
#define NTHREADS 128

__device__ float        g_cta[NCTAS];
__device__ unsigned int g_retired = 0;

__device__ __forceinline__ void acc_sq(const float4& a, const float4& b, float& s) {
    float d;
    d = a.x - b.x; s = fmaf(d, d, s);
    d = a.y - b.y; s = fmaf(d, d, s);
    d = a.z - b.z; s = fmaf(d, d, s);
    d = a.w - b.w; s = fmaf(d, d, s);
}

__global__ __launch_bounds__(NTHREADS, 16)
void triplet_fused_kernel(const float* __restrict__ f,
                          const float* __restrict__ label,
                          const int*   __restrict__ idx1,
                          const int*   __restrict__ idx2,
                          float* __restrict__ out) {
    const int lane  = threadIdx.x & 31;
    const int wid   = threadIdx.x >> 5;          // 0..3
    const int rloc  = wid >> 1;                  // 0..1 row within CTA
    const int half  = wid & 1;                   // which D-half
    const int row   = blockIdx.x * ROWS_PER_CTA + rloc;

    const int j1 = idx1[row];
    const int j2 = idx2[row];

    // Half-row base: 512 float4 per half
    const size_t hoff = (size_t)half * (NDIM / 8);   // float4 units: 512
    const float4* __restrict__ fi = (const float4*)(f + (size_t)row * NDIM) + hoff;
    const float4* __restrict__ f1 = (const float4*)(f + (size_t)j1  * NDIM) + hoff;
    const float4* __restrict__ f2 = (const float4*)(f + (size_t)j2  * NDIM) + hoff;

    float s1 = 0.0f;   // ||.||^2 partial vs idx1 (this half)
    float s2 = 0.0f;   // vs idx2

    // 512 float4 / 32 lanes = 16 steps; unroll x2 with front-batched loads:
    // 6 independent LDG.128 per lane between scoreboard waits.
    #pragma unroll
    for (int w = 0; w < 8; w++) {
        const int k0 = lane + (2 * w + 0) * 32;
        const int k1 = lane + (2 * w + 1) * 32;
        float4 a0 = fi[k0], b0 = f1[k0], c0 = f2[k0];
        float4 a1 = fi[k1], b1 = f1[k1], c1 = f2[k1];
        acc_sq(a0, b0, s1);
        acc_sq(a0, c0, s2);
        acc_sq(a1, b1, s1);
        acc_sq(a1, c1, s2);
    }

    // warp-local reduce (5 shuffle steps)
    #pragma unroll
    for (int off = 16; off > 0; off >>= 1) {
        s1 += __shfl_xor_sync(0xFFFFFFFFu, s1, off);
        s2 += __shfl_xor_sync(0xFFFFFFFFu, s2, off);
    }

    __shared__ float sh_s1[4];
    __shared__ float sh_s2[4];
    __shared__ float sh_loss[ROWS_PER_CTA];
    if (lane == 0) { sh_s1[wid] = s1; sh_s2[wid] = s2; }
    __syncthreads();

    if (half == 0 && lane == 0) {
        const float t1 = sh_s1[wid] + sh_s1[wid + 1];   // fixed order
        const float t2 = sh_s2[wid] + sh_s2[wid + 1];

        const float li = label[row];
        const float l1 = label[j1];
        const float l2 = label[j2];
        const float d1 = fabsf(li - l1);
        const float d2 = fabsf(li - l2);
        const bool cond = (d1 >= d2);            // true -> idx2 is the near sample
        const float a2n   = cond ? t2 : t1;
        const float a2f   = cond ? t1 : t2;
        const float nearl = cond ? l2 : l1;
        const float farl  = cond ? l1 : l2;
        const float dn = li - nearl;
        const float df = li - farl;
        const float alpha = df * df - dn * dn;
        const float loss = a2n - a2f + alpha * MARGIN;
        sh_loss[rloc] = fmaxf(loss, 0.0f);
    }
    __syncthreads();

    // ---- per-CTA sum + retirement ----
    __shared__ bool s_is_last;
    if (threadIdx.x == 0) {
        g_cta[blockIdx.x] = sh_loss[0] + sh_loss[1];    // fixed order
        __threadfence();            // make this CTA's sum globally visible
        unsigned int prev = atomicAdd(&g_retired, 1u);
        s_is_last = (prev == NCTAS - 1);
    }
    __syncthreads();

    // ---- last CTA: deterministic fixed-order final sum of 2048 values ----
    if (s_is_last) {
        __threadfence();            // see all other CTAs' sums
        float acc = 0.0f;
        #pragma unroll
        for (int k = 0; k < NCTAS / NTHREADS; k++)   // 16 strided reads per thread
            acc += g_cta[threadIdx.x + k * NTHREADS];

        #pragma unroll
        for (int off = 16; off > 0; off >>= 1)
            acc += __shfl_xor_sync(0xFFFFFFFFu, acc, off);

        __shared__ float shf[4];
        if (lane == 0) shf[wid] = acc;
        __syncthreads();
        if (wid == 0) {
            float t = (lane < 4) ? shf[lane] : 0.0f;
            #pragma unroll
            for (int off = 2; off > 0; off >>= 1)
                t += __shfl_xor_sync(0xFFFFFFFFu, t, off);
            if (lane == 0) {
                out[0] = t;
                g_retired = 0;      // reset for next graph replay
            }
        }
    }
}

extern "C" void kernel_launch(void* const* d_in, const int* in_sizes, int n_in,
                              void* d_out, int out_size) {
    const float* f     = (const float*)d_in[0];
    const float* label = (const float*)d_in[1];
    const int*   idx1  = (const int*)d_in[2];
    const int*   idx2  = (const int*)d_in[3];
    float* out = (float*)d_out;

    triplet_fused_kernel<<<NCTAS, NTHREADS>>>(f, label, idx1, idx2, out);
}